// round 6
// baseline (speedup 1.0000x reference)
#include <cuda_runtime.h>
#include <cuda_bf16.h>
#include <math.h>

// ---------------- scratch (static device globals) ------------------------------
__device__ float g_v [16777216];                 // v                  (B,64,N)
__device__ __nv_bfloat162 g_qh[8388608];         // q bf16 pairs       (B,32,N)
__device__ __nv_bfloat162 g_kh[8388608];         // k bf16 pairs       (B,32,N)
__device__ float g_xn[16777216];                 // x + attn_proj
__device__ unsigned long long g_ln[8388608];     // LN2 out, f32 pairs (B,32,N)
__device__ float g_m [67108864];                 // mlp_in output      (B,256,N)
__device__ float g_gt[16777216];                 // gated+BN
__device__ float g_sq[256];
__device__ float g_sk[256];
__device__ float g_sv[256];
__device__ float g_gram[2048];
__device__ float g_W[2048];                      // softmax weights, 1/||v|| folded
__device__ float g_M[16384];                     // per-batch proj*attn (4 x 64 x 64)

// ---------------- f32x2 helpers -------------------------------------------------
__device__ __forceinline__ unsigned long long pk2(float a, float b) {
    unsigned long long r;
    asm("mov.b64 %0, {%1, %2};" : "=l"(r) : "f"(a), "f"(b));
    return r;
}
__device__ __forceinline__ void fma2(unsigned long long& acc, unsigned long long w,
                                     unsigned long long v) {
    asm("fma.rn.f32x2 %0, %1, %2, %0;" : "+l"(acc) : "l"(w), "l"(v));
}
__device__ __forceinline__ float hadd2(unsigned long long a) {
    float lo, hi;
    asm("mov.b64 {%0, %1}, %2;" : "=f"(lo), "=f"(hi) : "l"(a));
    return lo + hi;
}

// ---------------- K0: zero accumulators -----------------------------------------
__global__ void k_zero() {
    int t = blockIdx.x * 256 + threadIdx.x;
    if (t < 256) { g_sq[t] = 0.f; g_sk[t] = 0.f; g_sv[t] = 0.f; }
    if (t < 2048) g_gram[t] = 0.f;
}

// ---------------- K1: fused LN1 + 3x3 depthwise + q/k/v GEMM --------------------
// tile 32x16 px, halo 34x18. smem: h[64][612] | wq|wk|wv[4096 ea] | dw[576] | ln w/b
#define HOFF   0
#define WQOFF  39168
#define WKOFF  43264
#define WVOFF  47360
#define DWOFF  51456
#define LWOFF  52032
#define LBOFF  52096
#define FRONT_SMEM (52160 * 4)

__global__ void __launch_bounds__(256) k_front(const float* __restrict__ x,
                                               const float* __restrict__ ln1w,
                                               const float* __restrict__ ln1b,
                                               const float* __restrict__ dww,
                                               const float* __restrict__ qw,
                                               const float* __restrict__ kw,
                                               const float* __restrict__ vw) {
    extern __shared__ __align__(16) float s[];
    int tid = threadIdx.x;
    for (int i = tid; i < 4096; i += 256) {
        s[WQOFF + i] = qw[i]; s[WKOFF + i] = kw[i]; s[WVOFF + i] = vw[i];
    }
    for (int i = tid; i < 576; i += 256) s[DWOFF + i] = dww[i];
    if (tid < 64) { s[LWOFF + tid] = ln1w[tid]; s[LBOFF + tid] = ln1b[tid]; }

    int tx0 = blockIdx.x << 5, ty0 = blockIdx.y << 4, bb = blockIdx.z;
    size_t bbase = (size_t)bb << 22;

    // --- LN1 into halo tile ---
    for (int i = tid; i < 612; i += 256) {
        int hy = i / 34, hx = i - hy * 34;
        int gx = tx0 + hx - 1, gy = ty0 + hy - 1;
        if ((unsigned)gx >= 256u || (unsigned)gy >= 256u) {
            #pragma unroll
            for (int c = 0; c < 64; c++) s[HOFF + c * 612 + i] = 0.f;
        } else {
            size_t base = bbase + ((size_t)gy << 8) + gx;
            float v[64]; float mu = 0.f;
            #pragma unroll
            for (int c = 0; c < 64; c++) { v[c] = x[base + ((size_t)c << 16)]; mu += v[c]; }
            mu *= 0.015625f;
            float var = 0.f;
            #pragma unroll
            for (int c = 0; c < 64; c++) { float d = v[c] - mu; var += d * d; }
            float rs = rsqrtf(var * 0.015625f + 1e-5f);
            #pragma unroll
            for (int c = 0; c < 64; c++)
                s[HOFF + c * 612 + i] = (v[c] - mu) * rs * s[LWOFF + c] + s[LBOFF + c];
        }
    }
    __syncthreads();

    // --- depthwise 3x3 for a vertical pixel pair ---
    int lx = tid & 31, tyy = tid >> 5;            // tyy 0..7
    int y0h = tyy << 1;                            // halo row of px0's top tap
    unsigned long long inA[32], inB[32];           // channel pairs, pixel A / pixel B
    #pragma unroll
    for (int cp = 0; cp < 32; cp++) {
        float dv[4];
        #pragma unroll
        for (int w = 0; w < 2; w++) {
            int c = (cp << 1) + w;
            const float* hc = s + HOFF + c * 612;
            const float* w9 = s + DWOFF + c * 9;
            float t[12];
            #pragma unroll
            for (int r = 0; r < 4; r++)
                #pragma unroll
                for (int cc = 0; cc < 3; cc++)
                    t[r * 3 + cc] = hc[(y0h + r) * 34 + lx + cc];
            float p0 = 0.f, p1 = 0.f;
            #pragma unroll
            for (int j = 0; j < 9; j++) { p0 += w9[j] * t[j]; p1 += w9[j] * t[j + 3]; }
            dv[w] = p0; dv[2 + w] = p1;
        }
        inA[cp] = pk2(dv[0], dv[1]);
        inB[cp] = pk2(dv[2], dv[3]);
    }

    // --- qkv GEMM: output pair (oa,ob) processed sequentially (6 accumulators) --
    size_t p0 = bbase + ((size_t)(ty0 + (tyy << 1)) << 8) + tx0 + lx;
    size_t p1 = p0 + 256;
    size_t hb = ((size_t)bb << 21) + (p0 & 0x3FFFFF);     // pair-array pixel base
    size_t hb1 = hb + 256;
    #pragma unroll 1
    for (int o2 = 0; o2 < 32; o2++) {
        int oa = o2 << 1, ob = oa + 1;
        float qaA, qaB, kaA, kaB, vaA, vaB;
        {   // output oa
            const ulonglong2* rq = (const ulonglong2*)(s + WQOFF + (oa << 6));
            const ulonglong2* rk = (const ulonglong2*)(s + WKOFF + (oa << 6));
            const ulonglong2* rv = (const ulonglong2*)(s + WVOFF + (oa << 6));
            unsigned long long q0=0,q1=0,k0=0,k1=0,v0=0,v1=0;
            #pragma unroll
            for (int c4 = 0; c4 < 16; c4++) {
                ulonglong2 wq = rq[c4], wk = rk[c4], wv = rv[c4];
                unsigned long long iA0 = inA[2*c4], iA1 = inA[2*c4+1];
                unsigned long long iB0 = inB[2*c4], iB1 = inB[2*c4+1];
                fma2(q0, wq.x, iA0); fma2(q0, wq.y, iA1);
                fma2(q1, wq.x, iB0); fma2(q1, wq.y, iB1);
                fma2(k0, wk.x, iA0); fma2(k0, wk.y, iA1);
                fma2(k1, wk.x, iB0); fma2(k1, wk.y, iB1);
                fma2(v0, wv.x, iA0); fma2(v0, wv.y, iA1);
                fma2(v1, wv.x, iB0); fma2(v1, wv.y, iB1);
            }
            qaA = hadd2(q0); qaB = hadd2(q1);
            kaA = hadd2(k0); kaB = hadd2(k1);
            vaA = hadd2(v0); vaB = hadd2(v1);
        }
        float qbA, qbB, kbA, kbB, vbA, vbB;
        {   // output ob
            const ulonglong2* rq = (const ulonglong2*)(s + WQOFF + (ob << 6));
            const ulonglong2* rk = (const ulonglong2*)(s + WKOFF + (ob << 6));
            const ulonglong2* rv = (const ulonglong2*)(s + WVOFF + (ob << 6));
            unsigned long long q0=0,q1=0,k0=0,k1=0,v0=0,v1=0;
            #pragma unroll
            for (int c4 = 0; c4 < 16; c4++) {
                ulonglong2 wq = rq[c4], wk = rk[c4], wv = rv[c4];
                unsigned long long iA0 = inA[2*c4], iA1 = inA[2*c4+1];
                unsigned long long iB0 = inB[2*c4], iB1 = inB[2*c4+1];
                fma2(q0, wq.x, iA0); fma2(q0, wq.y, iA1);
                fma2(q1, wq.x, iB0); fma2(q1, wq.y, iB1);
                fma2(k0, wk.x, iA0); fma2(k0, wk.y, iA1);
                fma2(k1, wk.x, iB0); fma2(k1, wk.y, iB1);
                fma2(v0, wv.x, iA0); fma2(v0, wv.y, iA1);
                fma2(v1, wv.x, iB0); fma2(v1, wv.y, iB1);
            }
            qbA = hadd2(q0); qbB = hadd2(q1);
            kbA = hadd2(k0); kbB = hadd2(k1);
            vbA = hadd2(v0); vbB = hadd2(v1);
        }
        g_qh[hb  + ((size_t)o2 << 16)] = __floats2bfloat162_rn(qaA, qbA);
        g_qh[hb1 + ((size_t)o2 << 16)] = __floats2bfloat162_rn(qaB, qbB);
        g_kh[hb  + ((size_t)o2 << 16)] = __floats2bfloat162_rn(kaA, kbA);
        g_kh[hb1 + ((size_t)o2 << 16)] = __floats2bfloat162_rn(kaB, kbB);
        g_v [p0 + ((size_t)oa << 16)] = vaA;
        g_v [p1 + ((size_t)oa << 16)] = vaB;
        g_v [p0 + ((size_t)ob << 16)] = vbA;
        g_v [p1 + ((size_t)ob << 16)] = vbB;
    }
}

// ---------------- K4: Gram + sum-of-squares reduction ---------------------------
__global__ void __launch_bounds__(256) k_stats() {
    int tid = threadIdx.x;
    int chunk = blockIdx.x, hh = blockIdx.y, bb = blockIdx.z;
    float aq[8] = {0}, ak[8] = {0}, av[8] = {0}, G[64] = {0};
    size_t hb2 = ((size_t)bb << 21);
    size_t vb  = ((size_t)bb << 22) + ((size_t)(hh << 3) << 16);
    for (int it = 0; it < 32; it++) {
        int p = chunk * 8192 + it * 256 + tid;
        float qv[8], kv[8], vv[8];
        #pragma unroll
        for (int jp = 0; jp < 4; jp++) {
            __nv_bfloat162 qp = g_qh[hb2 + ((size_t)(hh * 4 + jp) << 16) + p];
            __nv_bfloat162 kp = g_kh[hb2 + ((size_t)(hh * 4 + jp) << 16) + p];
            qv[2*jp] = __bfloat162float(qp.x); qv[2*jp+1] = __bfloat162float(qp.y);
            kv[2*jp] = __bfloat162float(kp.x); kv[2*jp+1] = __bfloat162float(kp.y);
        }
        #pragma unroll
        for (int j = 0; j < 8; j++) vv[j] = g_v[vb + ((size_t)j << 16) + p];
        #pragma unroll
        for (int j = 0; j < 8; j++) {
            aq[j] += qv[j]*qv[j]; ak[j] += kv[j]*kv[j]; av[j] += vv[j]*vv[j];
        }
        #pragma unroll
        for (int d = 0; d < 8; d++)
            #pragma unroll
            for (int e = 0; e < 8; e++) G[d*8+e] += qv[d]*kv[e];
    }
    #pragma unroll
    for (int off = 16; off; off >>= 1) {
        #pragma unroll
        for (int j = 0; j < 8; j++) {
            aq[j] += __shfl_xor_sync(~0u, aq[j], off);
            ak[j] += __shfl_xor_sync(~0u, ak[j], off);
            av[j] += __shfl_xor_sync(~0u, av[j], off);
        }
        #pragma unroll
        for (int j = 0; j < 64; j++) G[j] += __shfl_xor_sync(~0u, G[j], off);
    }
    __shared__ float red[88];
    if (tid < 88) red[tid] = 0.f;
    __syncthreads();
    if ((tid & 31) == 0) {
        #pragma unroll
        for (int j = 0; j < 8; j++) {
            atomicAdd(&red[j], aq[j]); atomicAdd(&red[8+j], ak[j]); atomicAdd(&red[16+j], av[j]);
        }
        #pragma unroll
        for (int j = 0; j < 64; j++) atomicAdd(&red[24+j], G[j]);
    }
    __syncthreads();
    if (tid < 8)        atomicAdd(&g_sq[bb*64 + hh*8 + tid],        red[tid]);
    else if (tid < 16)  atomicAdd(&g_sk[bb*64 + hh*8 + tid - 8],    red[tid]);
    else if (tid < 24)  atomicAdd(&g_sv[bb*64 + hh*8 + tid - 16],   red[tid]);
    else if (tid < 88)  atomicAdd(&g_gram[(bb*8 + hh)*64 + tid-24], red[tid]);
}

// ---------------- K5: softmax weights with v-norm folded ------------------------
__global__ void k_attw() {
    int t = threadIdx.x;
    int d = t & 7; int bh = t >> 3; int bb = bh >> 3; int hh = bh & 7;
    float nq = fmaxf(sqrtf(g_sq[bb*64 + hh*8 + d]), 1e-12f);
    const float scale = 0.35355339059327373f;
    float row[8]; float mx = -1e30f;
    #pragma unroll
    for (int e = 0; e < 8; e++) {
        float ne = fmaxf(sqrtf(g_sk[bb*64 + hh*8 + e]), 1e-12f);
        row[e] = g_gram[bh*64 + d*8 + e] * scale / (nq * ne);
        mx = fmaxf(mx, row[e]);
    }
    float sum = 0.f;
    #pragma unroll
    for (int e = 0; e < 8; e++) { row[e] = expf(row[e] - mx); sum += row[e]; }
    float inv = 1.f / sum;
    #pragma unroll
    for (int e = 0; e < 8; e++) {
        float nv = fmaxf(sqrtf(g_sv[bb*64 + hh*8 + e]), 1e-12f);
        g_W[bh*64 + d*8 + e] = row[e] * inv / nv;
    }
}

// ---------------- K5b: combined M_b = proj * blockdiag(W) -----------------------
__global__ void k_mix(const float* __restrict__ projw) {
    int bb = blockIdx.x; int oc = threadIdx.x;
    for (int c = 0; c < 64; c++) {
        int h = c >> 3, e = c & 7;
        float a = 0.f;
        #pragma unroll
        for (int d = 0; d < 8; d++)
            a += projw[oc*64 + (h<<3) + d] * g_W[((bb<<3) + h)*64 + (d<<3) + e];
        g_M[bb*4096 + oc*64 + c] = a;
    }
}

// ---------------- K6a: attn+proj + residual + LN2 (P=1) -------------------------
__global__ void __launch_bounds__(256) k_fuse1(const float* __restrict__ x,
                                               const float* __restrict__ ln2w,
                                               const float* __restrict__ ln2b) {
    __shared__ __align__(16) float sM[4096];
    __shared__ float slw[64], slb[64];
    int tid = threadIdx.x; int bb = blockIdx.y;
    for (int i = tid; i < 4096; i += 256) sM[i] = g_M[bb*4096 + i];
    if (tid < 64) { slw[tid] = ln2w[tid]; slb[tid] = ln2b[tid]; }
    __syncthreads();
    int pix = blockIdx.x * 256 + tid;
    size_t base = ((size_t)bb << 22) + pix;
    unsigned long long vp[32];
    #pragma unroll
    for (int c = 0; c < 32; c++) {
        float a = g_v[base + ((size_t)(2*c)   << 16)];
        float b = g_v[base + ((size_t)(2*c+1) << 16)];
        vp[c] = pk2(a, b);
    }
    float y[64]; float mu = 0.f;
    #pragma unroll
    for (int oc = 0; oc < 64; oc++) {
        const ulonglong2* row = (const ulonglong2*)(sM + (oc << 6));
        unsigned long long acc = 0ull;
        #pragma unroll
        for (int c4 = 0; c4 < 16; c4++) {
            ulonglong2 w2 = row[c4];
            fma2(acc, w2.x, vp[2*c4]); fma2(acc, w2.y, vp[2*c4+1]);
        }
        y[oc] = hadd2(acc) + x[base + ((size_t)oc << 16)];
        mu += y[oc];
    }
    mu *= 0.015625f;
    float var = 0.f;
    #pragma unroll
    for (int c = 0; c < 64; c++) {
        float d = y[c] - mu; var += d * d;
        g_xn[base + ((size_t)c << 16)] = y[c];
    }
    float rs = rsqrtf(var * 0.015625f + 1e-5f);
    size_t lnb = ((size_t)bb << 21) + pix;
    #pragma unroll
    for (int c = 0; c < 32; c++) {
        float a = (y[2*c]   - mu) * rs * slw[2*c]   + slb[2*c];
        float b = (y[2*c+1] - mu) * rs * slw[2*c+1] + slb[2*c+1];
        g_ln[lnb + ((size_t)c << 16)] = pk2(a, b);
    }
}

// ---------------- K6b: mlp_in GEMM (256 outputs), P=2 ---------------------------
__global__ void __launch_bounds__(256) k_fuse2(const float* __restrict__ mlpw) {
    extern __shared__ __align__(16) float sm2[];
    int tid = threadIdx.x; int bb = blockIdx.y;
    for (int i = tid; i < 16384; i += 256) sm2[i] = mlpw[i];
    __syncthreads();
    int px0 = blockIdx.x * 512 + tid;
    size_t lnb = ((size_t)bb << 21) + px0;
    unsigned long long lp0[32], lp1[32];
    #pragma unroll
    for (int c = 0; c < 32; c++) {
        lp0[c] = g_ln[lnb + ((size_t)c << 16)];
        lp1[c] = g_ln[lnb + 256 + ((size_t)c << 16)];
    }
    size_t mb0 = ((size_t)bb << 24) + px0;
    #pragma unroll 2
    for (int o = 0; o < 256; o++) {
        const ulonglong2* row = (const ulonglong2*)(sm2 + (o << 6));
        unsigned long long a0 = 0ull, a1 = 0ull;
        #pragma unroll
        for (int c4 = 0; c4 < 16; c4++) {
            ulonglong2 w2 = row[c4];
            fma2(a0, w2.x, lp0[2*c4]); fma2(a0, w2.y, lp0[2*c4+1]);
            fma2(a1, w2.x, lp1[2*c4]); fma2(a1, w2.y, lp1[2*c4+1]);
        }
        size_t oi = mb0 + ((size_t)o << 16);
        g_m[oi]       = hadd2(a0);
        g_m[oi + 256] = hadd2(a1);
    }
}

// ---------------- K7a: grouped 3x3 (reflect pad) + SiLU gate + BN ---------------
__global__ void __launch_bounds__(256) k_mlpdw(const float* __restrict__ dww,
                                               const float* __restrict__ bng,
                                               const float* __restrict__ bnb,
                                               const float* __restrict__ bnm,
                                               const float* __restrict__ bnv) {
    __shared__ float sw[4608];
    __shared__ float ssc[64], ssh[64];
    int tid = threadIdx.x;
    for (int i = tid; i < 4608; i += 256) sw[i] = dww[i];
    if (tid < 64) {
        float sc = bng[tid] * rsqrtf(bnv[tid] + 1e-5f);
        ssc[tid] = sc; ssh[tid] = bnb[tid] - bnm[tid] * sc;
    }
    __syncthreads();
    int t = blockIdx.x * 256 + tid;
    int p4 = t << 2;
    int bb = p4 >> 16, pix = p4 & 65535;
    int r = pix >> 8, c0 = pix & 255;
    int rm = r ? r - 1 : 1;
    int rp = (r == 255) ? 254 : r + 1;
    int ro0 = rm << 8, ro1 = r << 8, ro2 = rp << 8;
    int cols[6];
    #pragma unroll
    for (int k = 0; k < 6; k++) {
        int cx = c0 + k - 1;
        cols[k] = cx < 0 ? -cx : (cx > 255 ? 510 - cx : cx);
    }
    const float* mb = g_m + ((size_t)bb << 24);
    size_t obase = ((size_t)bb << 22) + pix;
    for (int cc = 0; cc < 32; cc++) {
        float A[4]={0,0,0,0}, Bx[4]={0,0,0,0}, Cx[4]={0,0,0,0}, Dx[4]={0,0,0,0};
        const float* w1a = sw + (2*cc)    * 36;
        const float* w1b = sw + (2*cc+1)  * 36;
        const float* w2a = sw + (64+2*cc) * 36;
        const float* w2b = sw + (65+2*cc) * 36;
        #pragma unroll
        for (int i = 0; i < 4; i++) {
            const float* p1 = mb + ((size_t)(4*cc + i)       << 16);
            const float* p2 = mb + ((size_t)(128 + 4*cc + i) << 16);
            float v1[18], v2[18];
            #pragma unroll
            for (int k = 0; k < 6; k++) {
                v1[k]    = p1[ro0 + cols[k]]; v1[6+k]  = p1[ro1 + cols[k]]; v1[12+k] = p1[ro2 + cols[k]];
                v2[k]    = p2[ro0 + cols[k]]; v2[6+k]  = p2[ro1 + cols[k]]; v2[12+k] = p2[ro2 + cols[k]];
            }
            #pragma unroll
            for (int ky = 0; ky < 3; ky++)
                #pragma unroll
                for (int kx = 0; kx < 3; kx++) {
                    float wa = w1a[i*9+ky*3+kx], wb = w1b[i*9+ky*3+kx];
                    float wc = w2a[i*9+ky*3+kx], wd = w2b[i*9+ky*3+kx];
                    #pragma unroll
                    for (int j = 0; j < 4; j++) {
                        float u1 = v1[ky*6 + j + kx], u2 = v2[ky*6 + j + kx];
                        A[j]  += wa * u1; Bx[j] += wb * u1;
                        Cx[j] += wc * u2; Dx[j] += wd * u2;
                    }
                }
        }
        int c1 = 2*cc, c2 = 2*cc + 1;
        float r1[4], r2[4];
        #pragma unroll
        for (int j = 0; j < 4; j++) {
            float s1 = A[j]  / (1.f + expf(-A[j]))  * Cx[j];
            float s2 = Bx[j] / (1.f + expf(-Bx[j])) * Dx[j];
            r1[j] = s1 * ssc[c1] + ssh[c1];
            r2[j] = s2 * ssc[c2] + ssh[c2];
        }
        *(float4*)(&g_gt[obase + ((size_t)c1 << 16)]) = make_float4(r1[0], r1[1], r1[2], r1[3]);
        *(float4*)(&g_gt[obase + ((size_t)c2 << 16)]) = make_float4(r2[0], r2[1], r2[2], r2[3]);
    }
}

// ---------------- K7b: out_w 1x1 + final residual, P=2 --------------------------
__global__ void __launch_bounds__(256) k_out(const float* __restrict__ ow,
                                             float* __restrict__ out) {
    __shared__ __align__(16) float s[4096];
    int tid = threadIdx.x;
    for (int i = tid; i < 4096; i += 256) s[i] = ow[i];
    __syncthreads();
    int px = blockIdx.x * 512 + tid; int bb = blockIdx.y;
    size_t base = ((size_t)bb << 22) + px;
    unsigned long long in0[32], in1[32];
    #pragma unroll
    for (int c = 0; c < 32; c++) {
        in0[c] = pk2(g_gt[base + ((size_t)(2*c) << 16)],
                     g_gt[base + ((size_t)(2*c+1) << 16)]);
        in1[c] = pk2(g_gt[base + 256 + ((size_t)(2*c) << 16)],
                     g_gt[base + 256 + ((size_t)(2*c+1) << 16)]);
    }
    #pragma unroll 2
    for (int oc = 0; oc < 64; oc++) {
        const ulonglong2* row = (const ulonglong2*)(s + (oc << 6));
        unsigned long long a0 = 0ull, a1 = 0ull;
        #pragma unroll
        for (int c4 = 0; c4 < 16; c4++) {
            ulonglong2 w2 = row[c4];
            fma2(a0, w2.x, in0[2*c4]); fma2(a0, w2.y, in0[2*c4+1]);
            fma2(a1, w2.x, in1[2*c4]); fma2(a1, w2.y, in1[2*c4+1]);
        }
        size_t oi = base + ((size_t)oc << 16);
        out[oi]       = g_xn[oi]       + hadd2(a0);
        out[oi + 256] = g_xn[oi + 256] + hadd2(a1);
    }
}

// ---------------- launch ---------------------------------------------------------
extern "C" void kernel_launch(void* const* d_in, const int* in_sizes, int n_in,
                              void* d_out, int out_size) {
    const float* x     = (const float*)d_in[0];
    const float* ln1w  = (const float*)d_in[1];
    const float* ln1b  = (const float*)d_in[2];
    const float* ln2w  = (const float*)d_in[3];
    const float* ln2b  = (const float*)d_in[4];
    const float* dww   = (const float*)d_in[5];
    const float* qw    = (const float*)d_in[6];
    const float* kw    = (const float*)d_in[7];
    const float* vw    = (const float*)d_in[8];
    const float* projw = (const float*)d_in[9];
    const float* mlpw  = (const float*)d_in[10];
    const float* mdww  = (const float*)d_in[11];
    const float* bng   = (const float*)d_in[12];
    const float* bnb   = (const float*)d_in[13];
    const float* bnm   = (const float*)d_in[14];
    const float* bnv   = (const float*)d_in[15];
    const float* ow    = (const float*)d_in[16];
    float* out = (float*)d_out;

    cudaFuncSetAttribute(k_front, cudaFuncAttributeMaxDynamicSharedMemorySize, FRONT_SMEM);
    cudaFuncSetAttribute(k_fuse2, cudaFuncAttributeMaxDynamicSharedMemorySize, 16384 * 4);

    k_zero<<<8, 256>>>();
    dim3 gfr(8, 16, 4);
    k_front<<<gfr, 256, FRONT_SMEM>>>(x, ln1w, ln1b, dww, qw, kw, vw);
    dim3 gs(8, 8, 4);
    k_stats<<<gs, 256>>>();
    k_attw<<<1, 256>>>();
    k_mix<<<4, 64>>>(projw);
    dim3 gf1(256, 4);
    k_fuse1<<<gf1, 256>>>(x, ln2w, ln2b);
    dim3 gf2(128, 4);
    k_fuse2<<<gf2, 256, 16384 * 4>>>(mlpw);
    k_mlpdw<<<256, 256>>>(mdww, bng, bnb, bnm, bnv);
    dim3 go(128, 4);
    k_out<<<go, 256>>>(ow, out);
}